// round 4
// baseline (speedup 1.0000x reference)
#include <cuda_runtime.h>
#include <cuda_bf16.h>

#define NN 100000
#define FF 256
#define DD 128
#define MM 10
#define BB 32768
#define KK 32

// ---------------- scratch (device globals; no allocation) ----------------
__device__ __align__(16) __nv_bfloat16 g_featbf[NN * FF];   // 51.2 MB feature in bf16
__device__ __align__(16) __nv_bfloat16 g_WbfT[DD * FF];     // Wemb transposed [n][k] bf16
__device__ __align__(16) __nv_bfloat16 g_flow_bf[NN * DD];  // 25.6 MB flow_all bf16
__device__ __align__(16) float g_agg[BB * DD];              // 16 MB
__device__ float g_score[NN];
__device__ __align__(16) float g_char[MM * DD];
__device__ __align__(16) float g_Lat[2 * MM * DD];
__device__ __align__(16) float g_cefeat[MM * FF];
__device__ float g_rowsum[MM];
__device__ __align__(16) float g_at[2 * DD];
__device__ __align__(16) float g_bb[MM * DD];

struct Ptrs {
    const float* wemb;
    const float* wchar;
    const float* lin1w;
    const int*   catr;
    const int*   catn;
    const int*   pa;
};
__device__ Ptrs g_ptrs;

// ---------------- K0: probe input ordering + zero accumulators ----------------
__global__ void fixup_kernel(const void* s0, const void* s1, const void* s2,
                             const void* s3, const void* s4, const void* s5,
                             const void* s6) {
    if (threadIdx.x == 0) {
        const unsigned* u = (const unsigned*)s0;
        bool intlike = true;
        for (int i = 0; i < 64; i++) {
            if (u[i] >= 100000u) { intlike = false; break; }
        }
        Ptrs p;
        if (intlike) {
            p.catr = (const int*)s1;  p.catn = (const int*)s2;  p.pa = (const int*)s3;
            p.wemb = (const float*)s4; p.wchar = (const float*)s5; p.lin1w = (const float*)s6;
        } else {
            p.wemb = (const float*)s0; p.wchar = (const float*)s1; p.lin1w = (const float*)s2;
            p.catr = (const int*)s4;  p.catn = (const int*)s5;  p.pa = (const int*)s6;
        }
        g_ptrs = p;
    }
    for (int i = threadIdx.x; i < MM * FF; i += blockDim.x) g_cefeat[i] = 0.f;
    if (threadIdx.x < MM) g_rowsum[threadIdx.x] = 0.f;
}

// ---------------- K0b: Wemb -> bf16 transposed [n][k] ----------------
__global__ void wcvt_kernel() {
    const int i = blockIdx.x * 256 + threadIdx.x;   // FF*DD = 32768
    if (i < FF * DD) {
        const int k = i / DD, n = i % DD;
        g_WbfT[n * FF + k] = __float2bfloat16(g_ptrs.wemb[i]);
    }
}

// ---------------- K1: ce_feat = adj @ feature ; rowsum ; feature->bf16 ----------------
__global__ __launch_bounds__(256) void adjfeat_kernel(const float* __restrict__ adj,
                                                      const float* __restrict__ feat) {
    __shared__ float adj_s[MM][512];
    const int n0  = blockIdx.x * 512;
    const int tid = threadIdx.x;
    const int lane = tid & 31;
    int limit = NN - n0;
    if (limit > 512) limit = 512;
    for (int m = 0; m < MM; m++)
        for (int j = tid; j < limit; j += 256)
            adj_s[m][j] = adj[(size_t)m * NN + n0 + j];
    __syncthreads();
    float acc[MM];
#pragma unroll
    for (int m = 0; m < MM; m++) acc[m] = 0.f;
    for (int j = 0; j < limit; j++) {
        const float v = feat[(size_t)(n0 + j) * FF + tid];
#pragma unroll
        for (int m = 0; m < MM; m++) acc[m] += adj_s[m][j] * v;
        // bf16 conversion write (pack pairs across lanes)
        const float vn = __shfl_down_sync(0xffffffffu, v, 1);
        if (!(lane & 1))
            *(__nv_bfloat162*)&g_featbf[(size_t)(n0 + j) * FF + tid] =
                __floats2bfloat162_rn(v, vn);
    }
#pragma unroll
    for (int m = 0; m < MM; m++) atomicAdd(&g_cefeat[m * FF + tid], acc[m]);
    const int warp = tid >> 5;
    for (int m = warp; m < MM; m += 8) {
        float s = 0.f;
        for (int j = lane; j < limit; j += 32) s += adj_s[m][j];
#pragma unroll
        for (int o = 16; o; o >>= 1) s += __shfl_xor_sync(0xffffffffu, s, o);
        if (lane == 0) atomicAdd(&g_rowsum[m], s);
    }
}

// ---------------- K2: char[m][d] = ce_feat[m] @ Wemb[:,d] + rowsum[m]*bias[d] ------------
__global__ __launch_bounds__(128) void char_kernel2(const float* __restrict__ bias) {
    __shared__ float ce[FF];
    const int m = blockIdx.x, d = threadIdx.x;
    for (int i = d; i < FF; i += 128) ce[i] = g_cefeat[m * FF + i];
    __syncthreads();
    const float* W = g_ptrs.wemb;
    float s = 0.f;
#pragma unroll 4
    for (int k = 0; k < FF; k++) s += ce[k] * W[(size_t)k * DD + d];
    g_char[m * DD + d] = s + g_rowsum[m] * bias[d];
}

// ---------------- K3: at / bb halves of the character GEMV ----------------
__global__ __launch_bounds__(128) void lat_kernel2() {
    __shared__ float ch[DD];
    const int b = blockIdx.x, d = threadIdx.x;
    const float* Wc = g_ptrs.wchar;
    if (b < 2) {
        for (int i = d; i < DD; i += 128) ch[i] = g_char[b * DD + i];
        __syncthreads();
        float s = 0.f;
#pragma unroll 4
        for (int i = 0; i < DD; i++) s += ch[i] * Wc[(size_t)i * DD + d];
        g_at[b * DD + d] = s;
    } else {
        const int m = b - 2;
        for (int i = d; i < DD; i += 128) ch[i] = g_char[m * DD + i];
        __syncthreads();
        float s = 0.f;
#pragma unroll 4
        for (int i = 0; i < DD; i++) s += ch[i] * Wc[(size_t)(DD + i) * DD + d];
        g_bb[m * DD + d] = s;
    }
}

// ---------------- K4: Lat table = sigmoid(at[c] + bb[p]) ----------------
__global__ void sig_kernel() {
    const int i = blockIdx.x * 256 + threadIdx.x;
    if (i >= 2 * MM * DD) return;
    const int d  = i & 127;
    const int p  = (i >> 7) % MM;
    const int cc = i / (MM * DD);
    g_Lat[i] = 1.f / (1.f + expf(-(g_at[cc * DD + d] + g_bb[p * DD + d])));
}

// ---------------- K5: bf16 tensor GEMM + fused flow_all(bf16) + score ----------------
// 128x128 block tile, K-chunk 32, 2-stage cp.async double buffer.
// mma.m16n8k16: warp w owns rows [w*16,w*16+16), 16 n-tiles.
__global__ __launch_bounds__(256) void gemm_fused(const float* __restrict__ bias,
                                                  const float* __restrict__ adj,
                                                  const float* __restrict__ att1w,
                                                  const float* __restrict__ att1b) {
    __shared__ __nv_bfloat16 As[2][128][40];   // pad 40: conflict-free frag loads
    __shared__ __nv_bfloat16 Bs[2][128][40];   // [n][k] layout
    __shared__ float att_s[DD], bias_s[DD], ch_s[2][DD];
    const int tid  = threadIdx.x;
    const int warp = tid >> 5, lane = tid & 31;
    const int gid  = lane >> 2, tig = lane & 3;
    const int row0 = blockIdx.x * 128;
    if (tid < DD) {
        att_s[tid]   = att1w[tid];
        bias_s[tid]  = bias[tid];
        ch_s[0][tid] = g_char[tid];
        ch_s[1][tid] = g_char[DD + tid];
    }

    float c[16][4];
#pragma unroll
    for (int nt = 0; nt < 16; nt++)
#pragma unroll
        for (int j = 0; j < 4; j++) c[nt][j] = 0.f;

    const int r_ld = tid >> 2, w_ld = (tid & 3);          // 64 rows per pass, 4 chunks/row
    auto load_stage = [&](int s, int kt) {
#pragma unroll
        for (int p = 0; p < 2; p++) {
            const int r = r_ld + p * 64;
            const int w = w_ld;
            unsigned da = (unsigned)__cvta_generic_to_shared(&As[s][r][w * 8]);
            const __nv_bfloat16* sa = g_featbf + (size_t)(row0 + r) * FF + kt + w * 8;
            const int sz = (row0 + r < NN) ? 16 : 0;
            asm volatile("cp.async.ca.shared.global [%0], [%1], 16, %2;"
                         :: "r"(da), "l"(sa), "r"(sz));
            unsigned db = (unsigned)__cvta_generic_to_shared(&Bs[s][r][w * 8]);
            const __nv_bfloat16* sb = g_WbfT + (size_t)r * FF + kt + w * 8;
            asm volatile("cp.async.ca.shared.global [%0], [%1], 16, 16;"
                         :: "r"(db), "l"(sb));
        }
    };

    load_stage(0, 0);
    asm volatile("cp.async.commit_group;");
    for (int it = 0; it < FF / 32; it++) {
        const int cur = it & 1;
        if (it < FF / 32 - 1) {
            load_stage(cur ^ 1, (it + 1) * 32);
            asm volatile("cp.async.commit_group;");
            asm volatile("cp.async.wait_group 1;");
        } else {
            asm volatile("cp.async.wait_group 0;");
        }
        __syncthreads();
#pragma unroll
        for (int kk = 0; kk < 32; kk += 16) {
            const unsigned a0 = *(const unsigned*)&As[cur][warp * 16 + gid    ][kk + tig * 2];
            const unsigned a1 = *(const unsigned*)&As[cur][warp * 16 + gid + 8][kk + tig * 2];
            const unsigned a2 = *(const unsigned*)&As[cur][warp * 16 + gid    ][kk + tig * 2 + 8];
            const unsigned a3 = *(const unsigned*)&As[cur][warp * 16 + gid + 8][kk + tig * 2 + 8];
#pragma unroll
            for (int nt = 0; nt < 16; nt++) {
                const unsigned b0 = *(const unsigned*)&Bs[cur][nt * 8 + gid][kk + tig * 2];
                const unsigned b1 = *(const unsigned*)&Bs[cur][nt * 8 + gid][kk + tig * 2 + 8];
                asm volatile(
                    "mma.sync.aligned.m16n8k16.row.col.f32.bf16.bf16.f32 "
                    "{%0,%1,%2,%3}, {%4,%5,%6,%7}, {%8,%9}, {%0,%1,%2,%3};"
                    : "+f"(c[nt][0]), "+f"(c[nt][1]), "+f"(c[nt][2]), "+f"(c[nt][3])
                    : "r"(a0), "r"(a1), "r"(a2), "r"(a3), "r"(b0), "r"(b1));
            }
        }
        __syncthreads();
    }

    // epilogue: bias, attribute mix, bf16 store, fused score
    const int r1 = row0 + warp * 16 + gid;
    const int r2 = r1 + 8;
    float a0r1 = 0.f, a1r1 = 0.f, a0r2 = 0.f, a1r2 = 0.f;
    if (r1 < NN) { a0r1 = adj[r1]; a1r1 = adj[NN + r1]; }
    if (r2 < NN) { a0r2 = adj[r2]; a1r2 = adj[NN + r2]; }
    float s1 = 0.f, s2 = 0.f;
#pragma unroll
    for (int nt = 0; nt < 16; nt++) {
        const int col = nt * 8 + tig * 2;
        const float ch0a = ch_s[0][col], ch0b = ch_s[0][col + 1];
        const float ch1a = ch_s[1][col], ch1b = ch_s[1][col + 1];
        const float ba = bias_s[col], bbv = bias_s[col + 1];
        const float v1a = 0.5f * (c[nt][0] + ba  + a0r1 * ch0a + a1r1 * ch1a);
        const float v1b = 0.5f * (c[nt][1] + bbv + a0r1 * ch0b + a1r1 * ch1b);
        const float v2a = 0.5f * (c[nt][2] + ba  + a0r2 * ch0a + a1r2 * ch1a);
        const float v2b = 0.5f * (c[nt][3] + bbv + a0r2 * ch0b + a1r2 * ch1b);
        if (r1 < NN)
            *(__nv_bfloat162*)&g_flow_bf[(size_t)r1 * DD + col] = __floats2bfloat162_rn(v1a, v1b);
        if (r2 < NN)
            *(__nv_bfloat162*)&g_flow_bf[(size_t)r2 * DD + col] = __floats2bfloat162_rn(v2a, v2b);
        s1 += v1a * att_s[col] + v1b * att_s[col + 1];
        s2 += v2a * att_s[col] + v2b * att_s[col + 1];
    }
    s1 += __shfl_xor_sync(0xffffffffu, s1, 1);
    s1 += __shfl_xor_sync(0xffffffffu, s1, 2);
    s2 += __shfl_xor_sync(0xffffffffu, s2, 1);
    s2 += __shfl_xor_sync(0xffffffffu, s2, 2);
    if (tig == 0) {
        const float b0 = att1b[0];
        if (r1 < NN) g_score[r1] = s1 + b0;
        if (r2 < NN) g_score[r2] = s2 + b0;
    }
}

// ---------------- K6: per-row gather + softmax + weighted sum (bf16 table) ---------------
__global__ __launch_bounds__(256) void agg_kernel(const int* __restrict__ history) {
    const int warp = threadIdx.x >> 5, lane = threadIdx.x & 31;
    const int b = blockIdx.x * 8 + warp;
    const int h = history[b * KK + lane];
    const float s = g_score[h];
    float mx = s;
#pragma unroll
    for (int o = 16; o; o >>= 1) mx = fmaxf(mx, __shfl_xor_sync(0xffffffffu, mx, o));
    const float e = expf(s - mx);
    float sum = e;
#pragma unroll
    for (int o = 16; o; o >>= 1) sum += __shfl_xor_sync(0xffffffffu, sum, o);
    const float att = e / sum;
    float4 acc = make_float4(0.f, 0.f, 0.f, 0.f);
    const uint2* fa = (const uint2*)g_flow_bf;
#pragma unroll
    for (int k = 0; k < KK; k++) {
        const int   idx = __shfl_sync(0xffffffffu, h, k);
        const float w   = __shfl_sync(0xffffffffu, att, k);
        const uint2 f = fa[idx * 32 + lane];
        const float2 p0 = __bfloat1622float2(*(const __nv_bfloat162*)&f.x);
        const float2 p1 = __bfloat1622float2(*(const __nv_bfloat162*)&f.y);
        acc.x += w * p0.x; acc.y += w * p0.y; acc.z += w * p1.x; acc.w += w * p1.y;
    }
    ((float4*)g_agg)[b * 32 + lane] = acc;
}

// ---------------- K7: out = relu(agg @ (W1_top+W1_bot) + b1); preds fused ----------------
__global__ __launch_bounds__(256) void outpred_kernel(const float* __restrict__ lin1b,
                                                      float* __restrict__ out) {
    __shared__ __align__(16) float As[8][132];
    __shared__ __align__(16) float Bs[8][132];
    __shared__ __align__(16) float Lat_s[2 * MM * DD];
    __shared__ __align__(16) float lb_s[DD];
    const float* lw   = g_ptrs.lin1w;
    const int*   catr = g_ptrs.catr;
    const int*   catn = g_ptrs.catn;
    const int*   pav  = g_ptrs.pa;
    const int tid  = threadIdx.x;
    const int row0 = blockIdx.x * 128;
    for (int i = tid; i < 2 * MM * DD; i += 256) Lat_s[i] = g_Lat[i];
    if (tid < DD) lb_s[tid] = lin1b[tid];
    const int aRow = tid >> 1, aCol = (tid & 1) * 4;
    const int bRow = tid >> 5, bCol = (tid & 31) * 4;
    const int tx = tid & 15, ty = tid >> 4;

    float acc[8][8];
#pragma unroll
    for (int i = 0; i < 8; i++)
#pragma unroll
        for (int j = 0; j < 8; j++) acc[i][j] = 0.f;

    for (int kt = 0; kt < DD; kt += 8) {
        float4 av = *(const float4*)(g_agg + (size_t)(row0 + aRow) * DD + kt + aCol);
        As[aCol + 0][aRow] = av.x;
        As[aCol + 1][aRow] = av.y;
        As[aCol + 2][aRow] = av.z;
        As[aCol + 3][aRow] = av.w;
        float4 b0 = *(const float4*)(lw + (size_t)(kt + bRow) * DD + bCol);
        float4 b1 = *(const float4*)(lw + (size_t)(DD + kt + bRow) * DD + bCol);
        float4 bv = make_float4(b0.x + b1.x, b0.y + b1.y, b0.z + b1.z, b0.w + b1.w);
        *(float4*)(&Bs[bRow][bCol]) = bv;
        __syncthreads();
#pragma unroll
        for (int kk = 0; kk < 8; kk++) {
            float ra[8], rb[8];
            *(float4*)(ra)     = *(const float4*)(&As[kk][ty * 8]);
            *(float4*)(ra + 4) = *(const float4*)(&As[kk][ty * 8 + 4]);
            *(float4*)(rb)     = *(const float4*)(&Bs[kk][tx * 8]);
            *(float4*)(rb + 4) = *(const float4*)(&Bs[kk][tx * 8 + 4]);
#pragma unroll
            for (int i = 0; i < 8; i++)
#pragma unroll
                for (int j = 0; j < 8; j++) acc[i][j] += ra[i] * rb[j];
        }
        __syncthreads();
    }

    float pr[8], pn[8];
#pragma unroll
    for (int i = 0; i < 8; i++) {
        const int row = row0 + ty * 8 + i;
        const int cr  = catr[row];
        const int cn_ = catn[row];
        const int p_  = pav[row];
        const float4* Lr = (const float4*)&Lat_s[(cr * MM + p_) * DD];
        const float4* Ln = (const float4*)&Lat_s[(cn_ * MM + p_) * DD];
        float sr = 0.f, sn = 0.f;
#pragma unroll
        for (int jj = 0; jj < 2; jj++) {
            float4 l1 = Lr[tx * 2 + jj];
            float4 l2 = Ln[tx * 2 + jj];
            float4 bb = *(const float4*)&lb_s[tx * 8 + jj * 4];
            const float o0 = fmaxf(acc[i][jj * 4 + 0] + bb.x, 0.f);
            const float o1 = fmaxf(acc[i][jj * 4 + 1] + bb.y, 0.f);
            const float o2 = fmaxf(acc[i][jj * 4 + 2] + bb.z, 0.f);
            const float o3 = fmaxf(acc[i][jj * 4 + 3] + bb.w, 0.f);
            sr += l1.x * o0 + l1.y * o1 + l1.z * o2 + l1.w * o3;
            sn += l2.x * o0 + l2.y * o1 + l2.z * o2 + l2.w * o3;
        }
        pr[i] = sr;
        pn[i] = sn;
    }
#pragma unroll
    for (int off = 1; off < 16; off <<= 1) {
#pragma unroll
        for (int i = 0; i < 8; i++) {
            pr[i] += __shfl_xor_sync(0xffffffffu, pr[i], off);
            pn[i] += __shfl_xor_sync(0xffffffffu, pn[i], off);
        }
    }
    if (tx == 0) {
#pragma unroll
        for (int i = 0; i < 8; i++) {
            const int row = row0 + ty * 8 + i;
            out[row]      = pr[i];
            out[BB + row] = pn[i];
        }
    }
}

// ---------------- host ----------------
extern "C" void kernel_launch(void* const* d_in, const int* in_sizes, int n_in,
                              void* d_out, int out_size) {
    const float* feat = nullptr;
    const float* adj  = nullptr;
    const int*   hist = nullptr;
    const float* b1   = nullptr;
    const void*  s32[8] = {nullptr};
    int n32 = 0;
    const float* s128[4] = {nullptr};
    int n128 = 0;

    for (int i = 0; i < n_in; i++) {
        const int sz = in_sizes[i];
        if (sz == NN * FF)      feat = (const float*)d_in[i];
        else if (sz == MM * NN) adj  = (const float*)d_in[i];
        else if (sz == BB * KK) hist = (const int*)d_in[i];
        else if (sz == BB)      { if (n32 < 8)  s32[n32++]  = d_in[i]; }
        else if (sz == DD)      { if (n128 < 4) s128[n128++] = (const float*)d_in[i]; }
        else if (sz == 1)       b1 = (const float*)d_in[i];
    }
    const float* bemb  = s128[0];
    const float* att1w = s128[1];
    const float* lin1b = s128[2];

    fixup_kernel<<<1, 256>>>(s32[0], s32[1], s32[2], s32[3], s32[4], s32[5], s32[6]);
    wcvt_kernel<<<(FF * DD + 255) / 256, 256>>>();
    adjfeat_kernel<<<(NN + 511) / 512, 256>>>(adj, feat);
    char_kernel2<<<MM, 128>>>(bemb);
    gemm_fused<<<(NN + 127) / 128, 256>>>(bemb, adj, att1w, b1);
    lat_kernel2<<<MM + 2, 128>>>();
    sig_kernel<<<10, 256>>>();
    agg_kernel<<<BB / 8, 256>>>(hist);
    outpred_kernel<<<BB / 128, 256>>>(lin1b, (float*)d_out);
}

// round 5
// speedup vs baseline: 1.6573x; 1.6573x over previous
#include <cuda_runtime.h>
#include <cuda_fp16.h>

#define NN 100000
#define FF 256
#define DD 128
#define MM 10
#define BB 32768
#define KK 32

// ---------------- scratch (device globals; no allocation) ----------------
__device__ __align__(16) __half g_WhT[DD * FF];       // Wemb transposed [n][k] fp16
__device__ __align__(16) __half g_flow_h[NN * DD];    // 25.6 MB flow_all fp16
__device__ __align__(16) float g_agg[BB * DD];        // 16 MB
__device__ float g_score[NN];
__device__ __align__(16) float g_char[MM * DD];
__device__ __align__(16) float g_Lat[2 * MM * DD];
__device__ __align__(16) float g_cefeat[MM * FF];
__device__ float g_rowsum[MM];
__device__ __align__(16) float g_at[2 * DD];
__device__ __align__(16) float g_bb[MM * DD];

struct Ptrs {
    const float* wemb;
    const float* wchar;
    const float* lin1w;
    const int*   catr;
    const int*   catn;
    const int*   pa;
};
__device__ Ptrs g_ptrs;

// ---------------- K0: probe input ordering + zero accumulators ----------------
__global__ void fixup_kernel(const void* s0, const void* s1, const void* s2,
                             const void* s3, const void* s4, const void* s5,
                             const void* s6) {
    if (threadIdx.x == 0) {
        const unsigned* u = (const unsigned*)s0;
        bool intlike = true;
        for (int i = 0; i < 64; i++) {
            if (u[i] >= 100000u) { intlike = false; break; }
        }
        Ptrs p;
        if (intlike) {
            p.catr = (const int*)s1;  p.catn = (const int*)s2;  p.pa = (const int*)s3;
            p.wemb = (const float*)s4; p.wchar = (const float*)s5; p.lin1w = (const float*)s6;
        } else {
            p.wemb = (const float*)s0; p.wchar = (const float*)s1; p.lin1w = (const float*)s2;
            p.catr = (const int*)s4;  p.catn = (const int*)s5;  p.pa = (const int*)s6;
        }
        g_ptrs = p;
    }
    const int t = threadIdx.x;
    for (int i = t; i < MM * FF; i += 256) g_cefeat[i] = 0.f;
    for (int i = t; i < MM * DD; i += 256) { g_char[i] = 0.f; g_bb[i] = 0.f; }
    for (int i = t; i < 2 * DD; i += 256) g_at[i] = 0.f;
    if (t < MM) g_rowsum[t] = 0.f;
}

// ---------------- K0b: Wemb -> fp16 transposed [n][k] ----------------
__global__ void wcvt_kernel() {
    const int i = blockIdx.x * 256 + threadIdx.x;   // FF*DD = 32768
    if (i < FF * DD) {
        const int k = i / DD, n = i % DD;
        g_WhT[n * FF + k] = __float2half(g_ptrs.wemb[i]);
    }
}

// ---------------- K1: ce_feat = adj @ feature  [10,256]; rowsum[10] ----------------
__global__ __launch_bounds__(256) void adjfeat_kernel(const float* __restrict__ adj,
                                                      const float* __restrict__ feat) {
    __shared__ float adj_s[MM][512];
    const int n0  = blockIdx.x * 512;
    const int tid = threadIdx.x;
    int limit = NN - n0;
    if (limit > 512) limit = 512;
    for (int m = 0; m < MM; m++)
        for (int j = tid; j < limit; j += 256)
            adj_s[m][j] = adj[(size_t)m * NN + n0 + j];
    __syncthreads();
    float acc[MM];
#pragma unroll
    for (int m = 0; m < MM; m++) acc[m] = 0.f;
    for (int j = 0; j < limit; j++) {
        const float v = feat[(size_t)(n0 + j) * FF + tid];
#pragma unroll
        for (int m = 0; m < MM; m++) acc[m] += adj_s[m][j] * v;
    }
#pragma unroll
    for (int m = 0; m < MM; m++) atomicAdd(&g_cefeat[m * FF + tid], acc[m]);
    const int warp = tid >> 5, lane = tid & 31;
    for (int m = warp; m < MM; m += 8) {
        float s = 0.f;
        for (int j = lane; j < limit; j += 32) s += adj_s[m][j];
#pragma unroll
        for (int o = 16; o; o >>= 1) s += __shfl_xor_sync(0xffffffffu, s, o);
        if (lane == 0) atomicAdd(&g_rowsum[m], s);
    }
}

// ---------------- K2: char[m][d] += ce_feat[m][k0:k0+32] @ W[k0:k0+32, d] ---------------
// K-split: grid = MM*8 blocks; chunk 0 also adds rowsum[m]*bias[d].
__global__ __launch_bounds__(128) void char_kernel2(const float* __restrict__ bias) {
    __shared__ float ce[32];
    const int m  = blockIdx.x >> 3;
    const int k0 = (blockIdx.x & 7) * 32;
    const int d  = threadIdx.x;
    if (d < 32) ce[d] = g_cefeat[m * FF + k0 + d];
    __syncthreads();
    const float* W = g_ptrs.wemb;
    float s = 0.f;
#pragma unroll
    for (int k = 0; k < 32; k++) s += ce[k] * W[(size_t)(k0 + k) * DD + d];
    if (k0 == 0) s += g_rowsum[m] * bias[d];
    atomicAdd(&g_char[m * DD + d], s);
}

// ---------------- K3: at / bb halves of the character GEMV (k-split x4) ---------------
__global__ __launch_bounds__(128) void lat_kernel2() {
    __shared__ float ch[32];
    const int t  = blockIdx.x >> 2;        // 0..11: 0-1 -> at, 2-11 -> bb
    const int k0 = (blockIdx.x & 3) * 32;
    const int d  = threadIdx.x;
    const float* Wc = g_ptrs.wchar;
    const int m = (t < 2) ? t : (t - 2);
    if (d < 32) ch[d] = g_char[m * DD + k0 + d];
    __syncthreads();
    float s = 0.f;
    if (t < 2) {
#pragma unroll
        for (int i = 0; i < 32; i++) s += ch[i] * Wc[(size_t)(k0 + i) * DD + d];
        atomicAdd(&g_at[t * DD + d], s);
    } else {
#pragma unroll
        for (int i = 0; i < 32; i++) s += ch[i] * Wc[(size_t)(DD + k0 + i) * DD + d];
        atomicAdd(&g_bb[m * DD + d], s);
    }
}

// ---------------- K4: Lat table = sigmoid(at[c] + bb[p]) ----------------
__global__ void sig_kernel() {
    const int i = blockIdx.x * 256 + threadIdx.x;
    if (i >= 2 * MM * DD) return;
    const int d  = i & 127;
    const int p  = (i >> 7) % MM;
    const int cc = i / (MM * DD);
    g_Lat[i] = 1.f / (1.f + expf(-(g_at[cc * DD + d] + g_bb[p * DD + d])));
}

// ---------------- K5: fp16 tensor GEMM + fused flow_all(fp16) + score ----------------
// 128x128 tile, K-chunk 32. A: fp32 LDG -> cvt fp16 -> smem (reg double-buffer).
// B: cp.async fp16 [n][k], smem double-buffer. One __syncthreads per chunk.
__global__ __launch_bounds__(256) void gemm_fused(const float* __restrict__ feat,
                                                  const float* __restrict__ bias,
                                                  const float* __restrict__ adj,
                                                  const float* __restrict__ att1w,
                                                  const float* __restrict__ att1b) {
    __shared__ __half As[2][128][40];   // pad 40 -> frag loads conflict-free
    __shared__ __half Bs[2][128][40];   // [n][k]
    __shared__ float att_s[DD], bias_s[DD], ch_s[2][DD];
    const int tid  = threadIdx.x;
    const int warp = tid >> 5, lane = tid & 31;
    const int gid  = lane >> 2, tig = lane & 3;
    const int row0 = blockIdx.x * 128;
    if (tid < DD) {
        att_s[tid]   = att1w[tid];
        bias_s[tid]  = bias[tid];
        ch_s[0][tid] = g_char[tid];
        ch_s[1][tid] = g_char[DD + tid];
    }

    float c[16][4];
#pragma unroll
    for (int nt = 0; nt < 16; nt++)
#pragma unroll
        for (int j = 0; j < 4; j++) c[nt][j] = 0.f;

    // A staging: thread -> row tid>>1, 16 floats at col (tid&1)*16
    const int arow = tid >> 1;
    const int acol = (tid & 1) * 16;
    const bool a_ok = (row0 + arow) < NN;
    float4 areg[4];
    auto ldA = [&](int kt) {
        const float* src = feat + (size_t)(row0 + arow) * FF + kt + acol;
        if (a_ok) {
#pragma unroll
            for (int cidx = 0; cidx < 4; cidx++)
                areg[cidx] = *(const float4*)(src + cidx * 4);
        } else {
#pragma unroll
            for (int cidx = 0; cidx < 4; cidx++)
                areg[cidx] = make_float4(0.f, 0.f, 0.f, 0.f);
        }
    };
    auto stA = [&](int s) {
#pragma unroll
        for (int cidx = 0; cidx < 4; cidx++) {
            __half2 h0 = __floats2half2_rn(areg[cidx].x, areg[cidx].y);
            __half2 h1 = __floats2half2_rn(areg[cidx].z, areg[cidx].w);
            *(__half2*)&As[s][arow][acol + cidx * 4]     = h0;
            *(__half2*)&As[s][arow][acol + cidx * 4 + 2] = h1;
        }
    };
    // B staging: thread -> n = tid>>1, two 16B chunks at k = (tid&1)*16, +8
    const int bn = tid >> 1;
    const int bk = (tid & 1) * 16;
    auto ldB = [&](int s, int kt) {
#pragma unroll
        for (int p = 0; p < 2; p++) {
            unsigned dst = (unsigned)__cvta_generic_to_shared(&Bs[s][bn][bk + p * 8]);
            const __half* src = g_WhT + (size_t)bn * FF + kt + bk + p * 8;
            asm volatile("cp.async.ca.shared.global [%0], [%1], 16;"
                         :: "r"(dst), "l"(src));
        }
    };

    ldA(0);
    ldB(0, 0);
    asm volatile("cp.async.commit_group;");
    stA(0);

    for (int it = 0; it < FF / 32; it++) {
        const int cur = it & 1, nxt = cur ^ 1;
        if (it < FF / 32 - 1) {
            ldA((it + 1) * 32);
            ldB(nxt, (it + 1) * 32);
            asm volatile("cp.async.commit_group;");
            asm volatile("cp.async.wait_group 1;");
        } else {
            asm volatile("cp.async.wait_group 0;");
        }
        __syncthreads();
#pragma unroll
        for (int kk = 0; kk < 32; kk += 16) {
            const unsigned a0 = *(const unsigned*)&As[cur][warp * 16 + gid    ][kk + tig * 2];
            const unsigned a1 = *(const unsigned*)&As[cur][warp * 16 + gid + 8][kk + tig * 2];
            const unsigned a2 = *(const unsigned*)&As[cur][warp * 16 + gid    ][kk + tig * 2 + 8];
            const unsigned a3 = *(const unsigned*)&As[cur][warp * 16 + gid + 8][kk + tig * 2 + 8];
#pragma unroll
            for (int nt = 0; nt < 16; nt++) {
                const unsigned b0 = *(const unsigned*)&Bs[cur][nt * 8 + gid][kk + tig * 2];
                const unsigned b1 = *(const unsigned*)&Bs[cur][nt * 8 + gid][kk + tig * 2 + 8];
                asm volatile(
                    "mma.sync.aligned.m16n8k16.row.col.f32.f16.f16.f32 "
                    "{%0,%1,%2,%3}, {%4,%5,%6,%7}, {%8,%9}, {%0,%1,%2,%3};"
                    : "+f"(c[nt][0]), "+f"(c[nt][1]), "+f"(c[nt][2]), "+f"(c[nt][3])
                    : "r"(a0), "r"(a1), "r"(a2), "r"(a3), "r"(b0), "r"(b1));
            }
        }
        if (it < FF / 32 - 1) stA(nxt);   // safe: nxt last read before this iter's sync
    }

    // epilogue: bias, attribute mix, fp16 store, fused score
    const int r1 = row0 + warp * 16 + gid;
    const int r2 = r1 + 8;
    float a0r1 = 0.f, a1r1 = 0.f, a0r2 = 0.f, a1r2 = 0.f;
    if (r1 < NN) { a0r1 = adj[r1]; a1r1 = adj[NN + r1]; }
    if (r2 < NN) { a0r2 = adj[r2]; a1r2 = adj[NN + r2]; }
    float s1 = 0.f, s2 = 0.f;
#pragma unroll
    for (int nt = 0; nt < 16; nt++) {
        const int col = nt * 8 + tig * 2;
        const float ch0a = ch_s[0][col], ch0b = ch_s[0][col + 1];
        const float ch1a = ch_s[1][col], ch1b = ch_s[1][col + 1];
        const float ba = bias_s[col], bbv = bias_s[col + 1];
        const float v1a = 0.5f * (c[nt][0] + ba  + a0r1 * ch0a + a1r1 * ch1a);
        const float v1b = 0.5f * (c[nt][1] + bbv + a0r1 * ch0b + a1r1 * ch1b);
        const float v2a = 0.5f * (c[nt][2] + ba  + a0r2 * ch0a + a1r2 * ch1a);
        const float v2b = 0.5f * (c[nt][3] + bbv + a0r2 * ch0b + a1r2 * ch1b);
        if (r1 < NN)
            *(__half2*)&g_flow_h[(size_t)r1 * DD + col] = __floats2half2_rn(v1a, v1b);
        if (r2 < NN)
            *(__half2*)&g_flow_h[(size_t)r2 * DD + col] = __floats2half2_rn(v2a, v2b);
        s1 += v1a * att_s[col] + v1b * att_s[col + 1];
        s2 += v2a * att_s[col] + v2b * att_s[col + 1];
    }
    s1 += __shfl_xor_sync(0xffffffffu, s1, 1);
    s1 += __shfl_xor_sync(0xffffffffu, s1, 2);
    s2 += __shfl_xor_sync(0xffffffffu, s2, 1);
    s2 += __shfl_xor_sync(0xffffffffu, s2, 2);
    if (tig == 0) {
        const float b0 = att1b[0];
        if (r1 < NN) g_score[r1] = s1 + b0;
        if (r2 < NN) g_score[r2] = s2 + b0;
    }
}

// ---------------- K6: per-row gather + softmax + weighted sum (fp16 table) ---------------
__global__ __launch_bounds__(256) void agg_kernel(const int* __restrict__ history) {
    const int warp = threadIdx.x >> 5, lane = threadIdx.x & 31;
    const int b = blockIdx.x * 8 + warp;
    const int h = history[b * KK + lane];
    const float s = g_score[h];
    float mx = s;
#pragma unroll
    for (int o = 16; o; o >>= 1) mx = fmaxf(mx, __shfl_xor_sync(0xffffffffu, mx, o));
    const float e = expf(s - mx);
    float sum = e;
#pragma unroll
    for (int o = 16; o; o >>= 1) sum += __shfl_xor_sync(0xffffffffu, sum, o);
    const float att = e / sum;
    float4 acc = make_float4(0.f, 0.f, 0.f, 0.f);
    const uint2* fa = (const uint2*)g_flow_h;
#pragma unroll
    for (int k = 0; k < KK; k++) {
        const int   idx = __shfl_sync(0xffffffffu, h, k);
        const float w   = __shfl_sync(0xffffffffu, att, k);
        const uint2 f = fa[idx * 32 + lane];
        const float2 p0 = __half22float2(*(const __half2*)&f.x);
        const float2 p1 = __half22float2(*(const __half2*)&f.y);
        acc.x += w * p0.x; acc.y += w * p0.y; acc.z += w * p1.x; acc.w += w * p1.y;
    }
    ((float4*)g_agg)[b * 32 + lane] = acc;
}

// ---------------- K7: out = relu(agg @ (W1_top+W1_bot) + b1); preds fused ----------------
__global__ __launch_bounds__(256) void outpred_kernel(const float* __restrict__ lin1b,
                                                      float* __restrict__ out) {
    __shared__ __align__(16) float As[8][132];
    __shared__ __align__(16) float Bs[8][132];
    __shared__ __align__(16) float Lat_s[2 * MM * DD];
    __shared__ __align__(16) float lb_s[DD];
    const float* lw   = g_ptrs.lin1w;
    const int*   catr = g_ptrs.catr;
    const int*   catn = g_ptrs.catn;
    const int*   pav  = g_ptrs.pa;
    const int tid  = threadIdx.x;
    const int row0 = blockIdx.x * 128;
    for (int i = tid; i < 2 * MM * DD; i += 256) Lat_s[i] = g_Lat[i];
    if (tid < DD) lb_s[tid] = lin1b[tid];
    const int aRow = tid >> 1, aCol = (tid & 1) * 4;
    const int bRow = tid >> 5, bCol = (tid & 31) * 4;
    const int tx = tid & 15, ty = tid >> 4;

    float acc[8][8];
#pragma unroll
    for (int i = 0; i < 8; i++)
#pragma unroll
        for (int j = 0; j < 8; j++) acc[i][j] = 0.f;

    for (int kt = 0; kt < DD; kt += 8) {
        float4 av = *(const float4*)(g_agg + (size_t)(row0 + aRow) * DD + kt + aCol);
        As[aCol + 0][aRow] = av.x;
        As[aCol + 1][aRow] = av.y;
        As[aCol + 2][aRow] = av.z;
        As[aCol + 3][aRow] = av.w;
        float4 b0 = *(const float4*)(lw + (size_t)(kt + bRow) * DD + bCol);
        float4 b1 = *(const float4*)(lw + (size_t)(DD + kt + bRow) * DD + bCol);
        float4 bv = make_float4(b0.x + b1.x, b0.y + b1.y, b0.z + b1.z, b0.w + b1.w);
        *(float4*)(&Bs[bRow][bCol]) = bv;
        __syncthreads();
#pragma unroll
        for (int kk = 0; kk < 8; kk++) {
            float ra[8], rb[8];
            *(float4*)(ra)     = *(const float4*)(&As[kk][ty * 8]);
            *(float4*)(ra + 4) = *(const float4*)(&As[kk][ty * 8 + 4]);
            *(float4*)(rb)     = *(const float4*)(&Bs[kk][tx * 8]);
            *(float4*)(rb + 4) = *(const float4*)(&Bs[kk][tx * 8 + 4]);
#pragma unroll
            for (int i = 0; i < 8; i++)
#pragma unroll
                for (int j = 0; j < 8; j++) acc[i][j] += ra[i] * rb[j];
        }
        __syncthreads();
    }

    float pr[8], pn[8];
#pragma unroll
    for (int i = 0; i < 8; i++) {
        const int row = row0 + ty * 8 + i;
        const int cr  = catr[row];
        const int cn_ = catn[row];
        const int p_  = pav[row];
        const float4* Lr = (const float4*)&Lat_s[(cr * MM + p_) * DD];
        const float4* Ln = (const float4*)&Lat_s[(cn_ * MM + p_) * DD];
        float sr = 0.f, sn = 0.f;
#pragma unroll
        for (int jj = 0; jj < 2; jj++) {
            float4 l1 = Lr[tx * 2 + jj];
            float4 l2 = Ln[tx * 2 + jj];
            float4 bb = *(const float4*)&lb_s[tx * 8 + jj * 4];
            const float o0 = fmaxf(acc[i][jj * 4 + 0] + bb.x, 0.f);
            const float o1 = fmaxf(acc[i][jj * 4 + 1] + bb.y, 0.f);
            const float o2 = fmaxf(acc[i][jj * 4 + 2] + bb.z, 0.f);
            const float o3 = fmaxf(acc[i][jj * 4 + 3] + bb.w, 0.f);
            sr += l1.x * o0 + l1.y * o1 + l1.z * o2 + l1.w * o3;
            sn += l2.x * o0 + l2.y * o1 + l2.z * o2 + l2.w * o3;
        }
        pr[i] = sr;
        pn[i] = sn;
    }
#pragma unroll
    for (int off = 1; off < 16; off <<= 1) {
#pragma unroll
        for (int i = 0; i < 8; i++) {
            pr[i] += __shfl_xor_sync(0xffffffffu, pr[i], off);
            pn[i] += __shfl_xor_sync(0xffffffffu, pn[i], off);
        }
    }
    if (tx == 0) {
#pragma unroll
        for (int i = 0; i < 8; i++) {
            const int row = row0 + ty * 8 + i;
            out[row]      = pr[i];
            out[BB + row] = pn[i];
        }
    }
}

// ---------------- host ----------------
extern "C" void kernel_launch(void* const* d_in, const int* in_sizes, int n_in,
                              void* d_out, int out_size) {
    const float* feat = nullptr;
    const float* adj  = nullptr;
    const int*   hist = nullptr;
    const float* b1   = nullptr;
    const void*  s32[8] = {nullptr};
    int n32 = 0;
    const float* s128[4] = {nullptr};
    int n128 = 0;

    for (int i = 0; i < n_in; i++) {
        const int sz = in_sizes[i];
        if (sz == NN * FF)      feat = (const float*)d_in[i];
        else if (sz == MM * NN) adj  = (const float*)d_in[i];
        else if (sz == BB * KK) hist = (const int*)d_in[i];
        else if (sz == BB)      { if (n32 < 8)  s32[n32++]  = d_in[i]; }
        else if (sz == DD)      { if (n128 < 4) s128[n128++] = (const float*)d_in[i]; }
        else if (sz == 1)       b1 = (const float*)d_in[i];
    }
    const float* bemb  = s128[0];
    const float* att1w = s128[1];
    const float* lin1b = s128[2];

    fixup_kernel<<<1, 256>>>(s32[0], s32[1], s32[2], s32[3], s32[4], s32[5], s32[6]);
    wcvt_kernel<<<(FF * DD + 255) / 256, 256>>>();
    adjfeat_kernel<<<(NN + 511) / 512, 256>>>(adj, feat);
    char_kernel2<<<MM * 8, 128>>>(bemb);
    gemm_fused<<<(NN + 127) / 128, 256>>>(feat, bemb, adj, att1w, b1);
    lat_kernel2<<<(MM + 2) * 4, 128>>>();
    sig_kernel<<<10, 256>>>();
    agg_kernel<<<BB / 8, 256>>>(hist);
    outpred_kernel<<<BB / 128, 256>>>(lin1b, (float*)d_out);
}

// round 6
// speedup vs baseline: 1.8432x; 1.1122x over previous
#include <cuda_runtime.h>
#include <cuda_fp16.h>

#define NN 100000
#define FF 256
#define DD 128
#define MM 10
#define BB 32768
#define KK 32

// ---------------- scratch (device globals; no allocation) ----------------
__device__ __align__(16) __half g_WhT[DD * FF];       // Wemb transposed [n][k] fp16
__device__ __align__(16) __half g_W1hT[DD * DD];      // (W1_top+W1_bot) transposed [n][k] fp16
__device__ __align__(16) __half g_flow_h[NN * DD];    // 25.6 MB flow_all fp16
__device__ __align__(16) __half g_agg_h[BB * DD];     // 8 MB agg fp16
__device__ float g_score[NN];
__device__ __align__(16) float g_char[MM * DD];
__device__ __align__(16) float g_Lat[2 * MM * DD];
__device__ __align__(16) float g_cefeat[MM * FF];
__device__ float g_rowsum[MM];
__device__ __align__(16) float g_at[2 * DD];
__device__ __align__(16) float g_bb[MM * DD];

struct Ptrs {
    const float* wemb;
    const float* wchar;
    const float* lin1w;
    const int*   catr;
    const int*   catn;
    const int*   pa;
};
__device__ Ptrs g_ptrs;

// ---------------- K0: probe input ordering + zero accumulators ----------------
__global__ void fixup_kernel(const void* s0, const void* s1, const void* s2,
                             const void* s3, const void* s4, const void* s5,
                             const void* s6) {
    if (threadIdx.x == 0) {
        const unsigned* u = (const unsigned*)s0;
        bool intlike = true;
        for (int i = 0; i < 64; i++) {
            if (u[i] >= 100000u) { intlike = false; break; }
        }
        Ptrs p;
        if (intlike) {
            p.catr = (const int*)s1;  p.catn = (const int*)s2;  p.pa = (const int*)s3;
            p.wemb = (const float*)s4; p.wchar = (const float*)s5; p.lin1w = (const float*)s6;
        } else {
            p.wemb = (const float*)s0; p.wchar = (const float*)s1; p.lin1w = (const float*)s2;
            p.catr = (const int*)s4;  p.catn = (const int*)s5;  p.pa = (const int*)s6;
        }
        g_ptrs = p;
    }
    const int t = threadIdx.x;
    for (int i = t; i < MM * FF; i += 256) g_cefeat[i] = 0.f;
    for (int i = t; i < MM * DD; i += 256) { g_char[i] = 0.f; g_bb[i] = 0.f; }
    for (int i = t; i < 2 * DD; i += 256) g_at[i] = 0.f;
    if (t < MM) g_rowsum[t] = 0.f;
}

// ---------------- K0b: Wemb -> fp16 [n][k]; (W1_top+W1_bot) -> fp16 [n][k] ---------------
__global__ void wcvt_kernel() {
    const int i = blockIdx.x * 256 + threadIdx.x;
    if (i < FF * DD) {
        const int k = i / DD, n = i % DD;
        g_WhT[n * FF + k] = __float2half(g_ptrs.wemb[i]);
    } else if (i < FF * DD + DD * DD) {
        const int j = i - FF * DD;
        const int k = j / DD, n = j % DD;
        const float* lw = g_ptrs.lin1w;
        g_W1hT[n * DD + k] = __float2half(lw[k * DD + n] + lw[(DD + k) * DD + n]);
    }
}

// ---------------- K1: ce_feat = adj @ feature  [10,256]; rowsum[10] ----------------
__global__ __launch_bounds__(256) void adjfeat_kernel(const float* __restrict__ adj,
                                                      const float* __restrict__ feat) {
    __shared__ float adj_s[MM][512];
    const int n0  = blockIdx.x * 512;
    const int tid = threadIdx.x;
    int limit = NN - n0;
    if (limit > 512) limit = 512;
    for (int m = 0; m < MM; m++)
        for (int j = tid; j < limit; j += 256)
            adj_s[m][j] = adj[(size_t)m * NN + n0 + j];
    __syncthreads();
    float acc[MM];
#pragma unroll
    for (int m = 0; m < MM; m++) acc[m] = 0.f;
    for (int j = 0; j < limit; j++) {
        const float v = feat[(size_t)(n0 + j) * FF + tid];
#pragma unroll
        for (int m = 0; m < MM; m++) acc[m] += adj_s[m][j] * v;
    }
#pragma unroll
    for (int m = 0; m < MM; m++) atomicAdd(&g_cefeat[m * FF + tid], acc[m]);
    const int warp = tid >> 5, lane = tid & 31;
    for (int m = warp; m < MM; m += 8) {
        float s = 0.f;
        for (int j = lane; j < limit; j += 32) s += adj_s[m][j];
#pragma unroll
        for (int o = 16; o; o >>= 1) s += __shfl_xor_sync(0xffffffffu, s, o);
        if (lane == 0) atomicAdd(&g_rowsum[m], s);
    }
}

// ---------------- K2: char[m][d] += ce_feat[m][k0:k0+32] @ W[k0:k0+32, d] ---------------
__global__ __launch_bounds__(128) void char_kernel2(const float* __restrict__ bias) {
    __shared__ float ce[32];
    const int m  = blockIdx.x >> 3;
    const int k0 = (blockIdx.x & 7) * 32;
    const int d  = threadIdx.x;
    if (d < 32) ce[d] = g_cefeat[m * FF + k0 + d];
    __syncthreads();
    const float* W = g_ptrs.wemb;
    float s = 0.f;
#pragma unroll
    for (int k = 0; k < 32; k++) s += ce[k] * W[(size_t)(k0 + k) * DD + d];
    if (k0 == 0) s += g_rowsum[m] * bias[d];
    atomicAdd(&g_char[m * DD + d], s);
}

// ---------------- K3: at / bb halves of the character GEMV (k-split x4) ---------------
__global__ __launch_bounds__(128) void lat_kernel2() {
    __shared__ float ch[32];
    const int t  = blockIdx.x >> 2;
    const int k0 = (blockIdx.x & 3) * 32;
    const int d  = threadIdx.x;
    const float* Wc = g_ptrs.wchar;
    const int m = (t < 2) ? t : (t - 2);
    if (d < 32) ch[d] = g_char[m * DD + k0 + d];
    __syncthreads();
    float s = 0.f;
    if (t < 2) {
#pragma unroll
        for (int i = 0; i < 32; i++) s += ch[i] * Wc[(size_t)(k0 + i) * DD + d];
        atomicAdd(&g_at[t * DD + d], s);
    } else {
#pragma unroll
        for (int i = 0; i < 32; i++) s += ch[i] * Wc[(size_t)(DD + k0 + i) * DD + d];
        atomicAdd(&g_bb[m * DD + d], s);
    }
}

// ---------------- K4: Lat table = sigmoid(at[c] + bb[p]) ----------------
__global__ void sig_kernel() {
    const int i = blockIdx.x * 256 + threadIdx.x;
    if (i >= 2 * MM * DD) return;
    const int d  = i & 127;
    const int p  = (i >> 7) % MM;
    const int cc = i / (MM * DD);
    g_Lat[i] = 1.f / (1.f + expf(-(g_at[cc * DD + d] + g_bb[p * DD + d])));
}

// ---------------- K5: fp16 tensor GEMM + fused flow_all(fp16) + score ----------------
__global__ __launch_bounds__(256) void gemm_fused(const float* __restrict__ feat,
                                                  const float* __restrict__ bias,
                                                  const float* __restrict__ adj,
                                                  const float* __restrict__ att1w,
                                                  const float* __restrict__ att1b) {
    __shared__ __half As[2][128][40];
    __shared__ __half Bs[2][128][40];
    __shared__ float att_s[DD], bias_s[DD], ch_s[2][DD];
    const int tid  = threadIdx.x;
    const int warp = tid >> 5, lane = tid & 31;
    const int gid  = lane >> 2, tig = lane & 3;
    const int row0 = blockIdx.x * 128;
    if (tid < DD) {
        att_s[tid]   = att1w[tid];
        bias_s[tid]  = bias[tid];
        ch_s[0][tid] = g_char[tid];
        ch_s[1][tid] = g_char[DD + tid];
    }

    float c[16][4];
#pragma unroll
    for (int nt = 0; nt < 16; nt++)
#pragma unroll
        for (int j = 0; j < 4; j++) c[nt][j] = 0.f;

    const int arow = tid >> 1;
    const int acol = (tid & 1) * 16;
    const bool a_ok = (row0 + arow) < NN;
    float4 areg[4];
    auto ldA = [&](int kt) {
        const float* src = feat + (size_t)(row0 + arow) * FF + kt + acol;
        if (a_ok) {
#pragma unroll
            for (int cidx = 0; cidx < 4; cidx++)
                areg[cidx] = *(const float4*)(src + cidx * 4);
        } else {
#pragma unroll
            for (int cidx = 0; cidx < 4; cidx++)
                areg[cidx] = make_float4(0.f, 0.f, 0.f, 0.f);
        }
    };
    auto stA = [&](int s) {
#pragma unroll
        for (int cidx = 0; cidx < 4; cidx++) {
            __half2 h0 = __floats2half2_rn(areg[cidx].x, areg[cidx].y);
            __half2 h1 = __floats2half2_rn(areg[cidx].z, areg[cidx].w);
            *(__half2*)&As[s][arow][acol + cidx * 4]     = h0;
            *(__half2*)&As[s][arow][acol + cidx * 4 + 2] = h1;
        }
    };
    const int bn = tid >> 1;
    const int bk = (tid & 1) * 16;
    auto ldB = [&](int s, int kt) {
#pragma unroll
        for (int p = 0; p < 2; p++) {
            unsigned dst = (unsigned)__cvta_generic_to_shared(&Bs[s][bn][bk + p * 8]);
            const __half* src = g_WhT + (size_t)bn * FF + kt + bk + p * 8;
            asm volatile("cp.async.ca.shared.global [%0], [%1], 16;"
                         :: "r"(dst), "l"(src));
        }
    };

    ldA(0);
    ldB(0, 0);
    asm volatile("cp.async.commit_group;");
    stA(0);

    for (int it = 0; it < FF / 32; it++) {
        const int cur = it & 1, nxt = cur ^ 1;
        if (it < FF / 32 - 1) {
            ldA((it + 1) * 32);
            ldB(nxt, (it + 1) * 32);
            asm volatile("cp.async.commit_group;");
            asm volatile("cp.async.wait_group 1;");
        } else {
            asm volatile("cp.async.wait_group 0;");
        }
        __syncthreads();
#pragma unroll
        for (int kk = 0; kk < 32; kk += 16) {
            const unsigned a0 = *(const unsigned*)&As[cur][warp * 16 + gid    ][kk + tig * 2];
            const unsigned a1 = *(const unsigned*)&As[cur][warp * 16 + gid + 8][kk + tig * 2];
            const unsigned a2 = *(const unsigned*)&As[cur][warp * 16 + gid    ][kk + tig * 2 + 8];
            const unsigned a3 = *(const unsigned*)&As[cur][warp * 16 + gid + 8][kk + tig * 2 + 8];
#pragma unroll
            for (int nt = 0; nt < 16; nt++) {
                const unsigned b0 = *(const unsigned*)&Bs[cur][nt * 8 + gid][kk + tig * 2];
                const unsigned b1 = *(const unsigned*)&Bs[cur][nt * 8 + gid][kk + tig * 2 + 8];
                asm volatile(
                    "mma.sync.aligned.m16n8k16.row.col.f32.f16.f16.f32 "
                    "{%0,%1,%2,%3}, {%4,%5,%6,%7}, {%8,%9}, {%0,%1,%2,%3};"
                    : "+f"(c[nt][0]), "+f"(c[nt][1]), "+f"(c[nt][2]), "+f"(c[nt][3])
                    : "r"(a0), "r"(a1), "r"(a2), "r"(a3), "r"(b0), "r"(b1));
            }
        }
        if (it < FF / 32 - 1) stA(nxt);
    }

    const int r1 = row0 + warp * 16 + gid;
    const int r2 = r1 + 8;
    float a0r1 = 0.f, a1r1 = 0.f, a0r2 = 0.f, a1r2 = 0.f;
    if (r1 < NN) { a0r1 = adj[r1]; a1r1 = adj[NN + r1]; }
    if (r2 < NN) { a0r2 = adj[r2]; a1r2 = adj[NN + r2]; }
    float s1 = 0.f, s2 = 0.f;
#pragma unroll
    for (int nt = 0; nt < 16; nt++) {
        const int col = nt * 8 + tig * 2;
        const float ch0a = ch_s[0][col], ch0b = ch_s[0][col + 1];
        const float ch1a = ch_s[1][col], ch1b = ch_s[1][col + 1];
        const float ba = bias_s[col], bbv = bias_s[col + 1];
        const float v1a = 0.5f * (c[nt][0] + ba  + a0r1 * ch0a + a1r1 * ch1a);
        const float v1b = 0.5f * (c[nt][1] + bbv + a0r1 * ch0b + a1r1 * ch1b);
        const float v2a = 0.5f * (c[nt][2] + ba  + a0r2 * ch0a + a1r2 * ch1a);
        const float v2b = 0.5f * (c[nt][3] + bbv + a0r2 * ch0b + a1r2 * ch1b);
        if (r1 < NN)
            *(__half2*)&g_flow_h[(size_t)r1 * DD + col] = __floats2half2_rn(v1a, v1b);
        if (r2 < NN)
            *(__half2*)&g_flow_h[(size_t)r2 * DD + col] = __floats2half2_rn(v2a, v2b);
        s1 += v1a * att_s[col] + v1b * att_s[col + 1];
        s2 += v2a * att_s[col] + v2b * att_s[col + 1];
    }
    s1 += __shfl_xor_sync(0xffffffffu, s1, 1);
    s1 += __shfl_xor_sync(0xffffffffu, s1, 2);
    s2 += __shfl_xor_sync(0xffffffffu, s2, 1);
    s2 += __shfl_xor_sync(0xffffffffu, s2, 2);
    if (tig == 0) {
        const float b0 = att1b[0];
        if (r1 < NN) g_score[r1] = s1 + b0;
        if (r2 < NN) g_score[r2] = s2 + b0;
    }
}

// ---------------- K6: per-row gather + softmax + weighted sum -> fp16 agg ---------------
__global__ __launch_bounds__(256) void agg_kernel(const int* __restrict__ history) {
    const int warp = threadIdx.x >> 5, lane = threadIdx.x & 31;
    const int b = blockIdx.x * 8 + warp;
    const int h = history[b * KK + lane];
    const float s = g_score[h];
    float mx = s;
#pragma unroll
    for (int o = 16; o; o >>= 1) mx = fmaxf(mx, __shfl_xor_sync(0xffffffffu, mx, o));
    const float e = expf(s - mx);
    float sum = e;
#pragma unroll
    for (int o = 16; o; o >>= 1) sum += __shfl_xor_sync(0xffffffffu, sum, o);
    const float att = e / sum;
    float4 acc = make_float4(0.f, 0.f, 0.f, 0.f);
    const uint2* fa = (const uint2*)g_flow_h;
#pragma unroll
    for (int k = 0; k < KK; k++) {
        const int   idx = __shfl_sync(0xffffffffu, h, k);
        const float w   = __shfl_sync(0xffffffffu, att, k);
        const uint2 f = fa[idx * 32 + lane];
        const float2 p0 = __half22float2(*(const __half2*)&f.x);
        const float2 p1 = __half22float2(*(const __half2*)&f.y);
        acc.x += w * p0.x; acc.y += w * p0.y; acc.z += w * p1.x; acc.w += w * p1.y;
    }
    __half2 h0 = __floats2half2_rn(acc.x, acc.y);
    __half2 h1 = __floats2half2_rn(acc.z, acc.w);
    uint2 st;
    st.x = *(unsigned*)&h0;
    st.y = *(unsigned*)&h1;
    *(uint2*)&g_agg_h[(size_t)b * DD + lane * 4] = st;
}

// ---------------- K7: fp16 tensor out-GEMM + fused relu/bias/Lat-dot epilogue -----------
// out = relu(agg @ (W1_top+W1_bot) + b1); pred_r/n = Lat[...] . out   (warp-quad reduce)
__global__ __launch_bounds__(256) void outpred_kernel(const float* __restrict__ lin1b,
                                                      float* __restrict__ out) {
    __shared__ __half As[128][40];
    __shared__ __half Bs[128][40];
    __shared__ float Lat_s[2 * MM * DD];
    __shared__ float lb_s[DD];
    const int*   catr = g_ptrs.catr;
    const int*   catn = g_ptrs.catn;
    const int*   pav  = g_ptrs.pa;
    const int tid  = threadIdx.x;
    const int warp = tid >> 5, lane = tid & 31;
    const int gid  = lane >> 2, tig = lane & 3;
    const int row0 = blockIdx.x * 128;
    for (int i = tid; i < 2 * MM * DD; i += 256) Lat_s[i] = g_Lat[i];
    if (tid < DD) lb_s[tid] = lin1b[tid];

    float c[16][4];
#pragma unroll
    for (int nt = 0; nt < 16; nt++)
#pragma unroll
        for (int j = 0; j < 4; j++) c[nt][j] = 0.f;

    const int arow = tid >> 1;           // 128 rows, 2 threads/row
    const int acol = (tid & 1) * 16;     // 16 halves each
#pragma unroll
    for (int kt = 0; kt < DD; kt += 32) {
        // stage A (agg fp16) and B (combined W1 fp16 [n][k])
        *(uint4*)&As[arow][acol]     = *(const uint4*)&g_agg_h[(size_t)(row0 + arow) * DD + kt + acol];
        *(uint4*)&As[arow][acol + 8] = *(const uint4*)&g_agg_h[(size_t)(row0 + arow) * DD + kt + acol + 8];
        *(uint4*)&Bs[arow][acol]     = *(const uint4*)&g_W1hT[(size_t)arow * DD + kt + acol];
        *(uint4*)&Bs[arow][acol + 8] = *(const uint4*)&g_W1hT[(size_t)arow * DD + kt + acol + 8];
        __syncthreads();
#pragma unroll
        for (int kk = 0; kk < 32; kk += 16) {
            const unsigned a0 = *(const unsigned*)&As[warp * 16 + gid    ][kk + tig * 2];
            const unsigned a1 = *(const unsigned*)&As[warp * 16 + gid + 8][kk + tig * 2];
            const unsigned a2 = *(const unsigned*)&As[warp * 16 + gid    ][kk + tig * 2 + 8];
            const unsigned a3 = *(const unsigned*)&As[warp * 16 + gid + 8][kk + tig * 2 + 8];
#pragma unroll
            for (int nt = 0; nt < 16; nt++) {
                const unsigned b0 = *(const unsigned*)&Bs[nt * 8 + gid][kk + tig * 2];
                const unsigned b1 = *(const unsigned*)&Bs[nt * 8 + gid][kk + tig * 2 + 8];
                asm volatile(
                    "mma.sync.aligned.m16n8k16.row.col.f32.f16.f16.f32 "
                    "{%0,%1,%2,%3}, {%4,%5,%6,%7}, {%8,%9}, {%0,%1,%2,%3};"
                    : "+f"(c[nt][0]), "+f"(c[nt][1]), "+f"(c[nt][2]), "+f"(c[nt][3])
                    : "r"(a0), "r"(a1), "r"(a2), "r"(a3), "r"(b0), "r"(b1));
            }
        }
        __syncthreads();
    }

    // epilogue: relu(out+bias), dot with Lat rows for (cat_r,pa) and (cat_n,pa)
    const int r1 = row0 + warp * 16 + gid;
    const int r2 = r1 + 8;
    const int p1_ = pav[r1], p2_ = pav[r2];
    const float* Lr1 = &Lat_s[(catr[r1] * MM + p1_) * DD];
    const float* Ln1 = &Lat_s[(catn[r1] * MM + p1_) * DD];
    const float* Lr2 = &Lat_s[(catr[r2] * MM + p2_) * DD];
    const float* Ln2 = &Lat_s[(catn[r2] * MM + p2_) * DD];
    float sr1 = 0.f, sn1 = 0.f, sr2 = 0.f, sn2 = 0.f;
#pragma unroll
    for (int nt = 0; nt < 16; nt++) {
        const int col = nt * 8 + tig * 2;
        const float b0 = lb_s[col], b1 = lb_s[col + 1];
        const float o0 = fmaxf(c[nt][0] + b0, 0.f);
        const float o1 = fmaxf(c[nt][1] + b1, 0.f);
        const float o2 = fmaxf(c[nt][2] + b0, 0.f);
        const float o3 = fmaxf(c[nt][3] + b1, 0.f);
        sr1 += o0 * Lr1[col] + o1 * Lr1[col + 1];
        sn1 += o0 * Ln1[col] + o1 * Ln1[col + 1];
        sr2 += o2 * Lr2[col] + o3 * Lr2[col + 1];
        sn2 += o2 * Ln2[col] + o3 * Ln2[col + 1];
    }
#pragma unroll
    for (int o = 1; o < 4; o <<= 1) {
        sr1 += __shfl_xor_sync(0xffffffffu, sr1, o);
        sn1 += __shfl_xor_sync(0xffffffffu, sn1, o);
        sr2 += __shfl_xor_sync(0xffffffffu, sr2, o);
        sn2 += __shfl_xor_sync(0xffffffffu, sn2, o);
    }
    if (tig == 0) {
        out[r1]      = sr1;
        out[BB + r1] = sn1;
        out[r2]      = sr2;
        out[BB + r2] = sn2;
    }
}

// ---------------- host ----------------
extern "C" void kernel_launch(void* const* d_in, const int* in_sizes, int n_in,
                              void* d_out, int out_size) {
    const float* feat = nullptr;
    const float* adj  = nullptr;
    const int*   hist = nullptr;
    const float* b1   = nullptr;
    const void*  s32[8] = {nullptr};
    int n32 = 0;
    const float* s128[4] = {nullptr};
    int n128 = 0;

    for (int i = 0; i < n_in; i++) {
        const int sz = in_sizes[i];
        if (sz == NN * FF)      feat = (const float*)d_in[i];
        else if (sz == MM * NN) adj  = (const float*)d_in[i];
        else if (sz == BB * KK) hist = (const int*)d_in[i];
        else if (sz == BB)      { if (n32 < 8)  s32[n32++]  = d_in[i]; }
        else if (sz == DD)      { if (n128 < 4) s128[n128++] = (const float*)d_in[i]; }
        else if (sz == 1)       b1 = (const float*)d_in[i];
    }
    const float* bemb  = s128[0];
    const float* att1w = s128[1];
    const float* lin1b = s128[2];

    fixup_kernel<<<1, 256>>>(s32[0], s32[1], s32[2], s32[3], s32[4], s32[5], s32[6]);
    wcvt_kernel<<<(FF * DD + DD * DD + 255) / 256, 256>>>();
    adjfeat_kernel<<<(NN + 511) / 512, 256>>>(adj, feat);
    char_kernel2<<<MM * 8, 128>>>(bemb);
    gemm_fused<<<(NN + 127) / 128, 256>>>(feat, bemb, adj, att1w, b1);
    lat_kernel2<<<(MM + 2) * 4, 128>>>();
    sig_kernel<<<10, 256>>>();
    agg_kernel<<<BB / 8, 256>>>(hist);
    outpred_kernel<<<BB / 128, 256>>>(lin1b, (float*)d_out);
}

// round 7
// speedup vs baseline: 1.8835x; 1.0219x over previous
#include <cuda_runtime.h>
#include <cuda_fp16.h>

#define NN 100000
#define FF 256
#define DD 128
#define MM 10
#define BB 32768
#define KK 32

// ---------------- scratch (device globals; no allocation) ----------------
__device__ __align__(16) __half g_WhT[DD * FF];       // Wemb transposed [n][k] fp16
__device__ __align__(16) __half g_W1hT[DD * DD];      // (W1_top+W1_bot) transposed [n][k] fp16
__device__ __align__(16) __half g_flow_h[NN * DD];    // 25.6 MB flow_all fp16
__device__ __align__(16) __half g_agg_h[BB * DD];     // 8 MB agg fp16
__device__ float g_score[NN];
__device__ __align__(16) float g_char[MM * DD];
__device__ __align__(16) float g_cefeat[MM * FF];
__device__ float g_rowsum[MM];
__device__ __align__(16) float g_at[2 * DD];
__device__ __align__(16) float g_bb[MM * DD];

struct Ptrs {
    const float* wemb;
    const float* wchar;
    const float* lin1w;
    const int*   catr;
    const int*   catn;
    const int*   pa;
};
__device__ Ptrs g_ptrs;

// ---------------- K0: probe input ordering + zero accumulators ----------------
__global__ void fixup_kernel(const void* s0, const void* s1, const void* s2,
                             const void* s3, const void* s4, const void* s5,
                             const void* s6) {
    if (threadIdx.x == 0) {
        const unsigned* u = (const unsigned*)s0;
        bool intlike = true;
        for (int i = 0; i < 64; i++) {
            if (u[i] >= 100000u) { intlike = false; break; }
        }
        Ptrs p;
        if (intlike) {
            p.catr = (const int*)s1;  p.catn = (const int*)s2;  p.pa = (const int*)s3;
            p.wemb = (const float*)s4; p.wchar = (const float*)s5; p.lin1w = (const float*)s6;
        } else {
            p.wemb = (const float*)s0; p.wchar = (const float*)s1; p.lin1w = (const float*)s2;
            p.catr = (const int*)s4;  p.catn = (const int*)s5;  p.pa = (const int*)s6;
        }
        g_ptrs = p;
    }
    const int t = threadIdx.x;
    for (int i = t; i < MM * FF; i += 256) g_cefeat[i] = 0.f;
    for (int i = t; i < MM * DD; i += 256) { g_char[i] = 0.f; g_bb[i] = 0.f; }
    for (int i = t; i < 2 * DD; i += 256) g_at[i] = 0.f;
    if (t < MM) g_rowsum[t] = 0.f;
}

// ---------------- K0b: Wemb -> fp16 [n][k]; (W1_top+W1_bot) -> fp16 [n][k] ---------------
__global__ void wcvt_kernel() {
    const int i = blockIdx.x * 256 + threadIdx.x;
    if (i < FF * DD) {
        const int k = i / DD, n = i % DD;
        g_WhT[n * FF + k] = __float2half(g_ptrs.wemb[i]);
    } else if (i < FF * DD + DD * DD) {
        const int j = i - FF * DD;
        const int k = j / DD, n = j % DD;
        const float* lw = g_ptrs.lin1w;
        g_W1hT[n * DD + k] = __float2half(lw[k * DD + n] + lw[(DD + k) * DD + n]);
    }
}

// ---------------- K1: ce_feat = adj @ feature  [10,256]; rowsum[10] ----------------
__global__ __launch_bounds__(256) void adjfeat_kernel(const float* __restrict__ adj,
                                                      const float* __restrict__ feat) {
    __shared__ float adj_s[MM][512];
    const int n0  = blockIdx.x * 512;
    const int tid = threadIdx.x;
    int limit = NN - n0;
    if (limit > 512) limit = 512;
    for (int m = 0; m < MM; m++)
        for (int j = tid; j < limit; j += 256)
            adj_s[m][j] = adj[(size_t)m * NN + n0 + j];
    __syncthreads();
    float acc[MM];
#pragma unroll
    for (int m = 0; m < MM; m++) acc[m] = 0.f;
    for (int j = 0; j < limit; j++) {
        const float v = feat[(size_t)(n0 + j) * FF + tid];
#pragma unroll
        for (int m = 0; m < MM; m++) acc[m] += adj_s[m][j] * v;
    }
#pragma unroll
    for (int m = 0; m < MM; m++) atomicAdd(&g_cefeat[m * FF + tid], acc[m]);
    const int warp = tid >> 5, lane = tid & 31;
    for (int m = warp; m < MM; m += 8) {
        float s = 0.f;
        for (int j = lane; j < limit; j += 32) s += adj_s[m][j];
#pragma unroll
        for (int o = 16; o; o >>= 1) s += __shfl_xor_sync(0xffffffffu, s, o);
        if (lane == 0) atomicAdd(&g_rowsum[m], s);
    }
}

// ---------------- K2: char[m][d] += ce_feat[m][k0:k0+32] @ W[k0:k0+32, d] ---------------
__global__ __launch_bounds__(128) void char_kernel2(const float* __restrict__ bias) {
    __shared__ float ce[32];
    const int m  = blockIdx.x >> 3;
    const int k0 = (blockIdx.x & 7) * 32;
    const int d  = threadIdx.x;
    if (d < 32) ce[d] = g_cefeat[m * FF + k0 + d];
    __syncthreads();
    const float* W = g_ptrs.wemb;
    float s = 0.f;
#pragma unroll
    for (int k = 0; k < 32; k++) s += ce[k] * W[(size_t)(k0 + k) * DD + d];
    if (k0 == 0) s += g_rowsum[m] * bias[d];
    atomicAdd(&g_char[m * DD + d], s);
}

// ---------------- K3: at / bb halves of the character GEMV (k-split x4) ---------------
__global__ __launch_bounds__(128) void lat_kernel2() {
    __shared__ float ch[32];
    const int t  = blockIdx.x >> 2;
    const int k0 = (blockIdx.x & 3) * 32;
    const int d  = threadIdx.x;
    const float* Wc = g_ptrs.wchar;
    const int m = (t < 2) ? t : (t - 2);
    if (d < 32) ch[d] = g_char[m * DD + k0 + d];
    __syncthreads();
    float s = 0.f;
    if (t < 2) {
#pragma unroll
        for (int i = 0; i < 32; i++) s += ch[i] * Wc[(size_t)(k0 + i) * DD + d];
        atomicAdd(&g_at[t * DD + d], s);
    } else {
#pragma unroll
        for (int i = 0; i < 32; i++) s += ch[i] * Wc[(size_t)(DD + k0 + i) * DD + d];
        atomicAdd(&g_bb[m * DD + d], s);
    }
}

// ---------------- K5: fp16 tensor GEMM + fused flow_all(fp16) + score ----------------
// Warp tiling 32x64 (4 m-warps x 2 n-warps): B fragments shared across 2 m-tiles,
// cutting smem crossbar traffic 73.7KB -> 49KB per K-chunk (now tensor-bound).
// Per-row score is split across 2 n-warps -> smem atomic partial + block reduce.
__global__ __launch_bounds__(256) void gemm_fused(const float* __restrict__ feat,
                                                  const float* __restrict__ bias,
                                                  const float* __restrict__ adj,
                                                  const float* __restrict__ att1w,
                                                  const float* __restrict__ att1b) {
    __shared__ __half As[2][128][40];
    __shared__ __half Bs[2][128][40];
    __shared__ float att_s[DD], bias_s[DD], ch_s[2][DD];
    __shared__ float sc[128];
    const int tid  = threadIdx.x;
    const int warp = tid >> 5, lane = tid & 31;
    const int gid  = lane >> 2, tig = lane & 3;
    const int wm   = warp & 3, wn = warp >> 2;     // 4 m-warps x 2 n-warps
    const int row0 = blockIdx.x * 128;
    if (tid < DD) {
        att_s[tid]   = att1w[tid];
        bias_s[tid]  = bias[tid];
        ch_s[0][tid] = g_char[tid];
        ch_s[1][tid] = g_char[DD + tid];
        sc[tid]      = 0.f;
    }

    float c[2][8][4];
#pragma unroll
    for (int mt = 0; mt < 2; mt++)
#pragma unroll
        for (int nt = 0; nt < 8; nt++)
#pragma unroll
            for (int j = 0; j < 4; j++) c[mt][nt][j] = 0.f;

    const int arow = tid >> 1;
    const int acol = (tid & 1) * 16;
    const bool a_ok = (row0 + arow) < NN;
    float4 areg[4];
    auto ldA = [&](int kt) {
        const float* src = feat + (size_t)(row0 + arow) * FF + kt + acol;
        if (a_ok) {
#pragma unroll
            for (int cidx = 0; cidx < 4; cidx++)
                areg[cidx] = *(const float4*)(src + cidx * 4);
        } else {
#pragma unroll
            for (int cidx = 0; cidx < 4; cidx++)
                areg[cidx] = make_float4(0.f, 0.f, 0.f, 0.f);
        }
    };
    auto stA = [&](int s) {
#pragma unroll
        for (int cidx = 0; cidx < 4; cidx++) {
            __half2 h0 = __floats2half2_rn(areg[cidx].x, areg[cidx].y);
            __half2 h1 = __floats2half2_rn(areg[cidx].z, areg[cidx].w);
            *(__half2*)&As[s][arow][acol + cidx * 4]     = h0;
            *(__half2*)&As[s][arow][acol + cidx * 4 + 2] = h1;
        }
    };
    const int bn = tid >> 1;
    const int bk = (tid & 1) * 16;
    auto ldB = [&](int s, int kt) {
#pragma unroll
        for (int p = 0; p < 2; p++) {
            unsigned dst = (unsigned)__cvta_generic_to_shared(&Bs[s][bn][bk + p * 8]);
            const __half* src = g_WhT + (size_t)bn * FF + kt + bk + p * 8;
            asm volatile("cp.async.ca.shared.global [%0], [%1], 16;"
                         :: "r"(dst), "l"(src));
        }
    };

    ldA(0);
    ldB(0, 0);
    asm volatile("cp.async.commit_group;");
    stA(0);

    for (int it = 0; it < FF / 32; it++) {
        const int cur = it & 1, nxt = cur ^ 1;
        if (it < FF / 32 - 1) {
            ldA((it + 1) * 32);
            ldB(nxt, (it + 1) * 32);
            asm volatile("cp.async.commit_group;");
            asm volatile("cp.async.wait_group 1;");
        } else {
            asm volatile("cp.async.wait_group 0;");
        }
        __syncthreads();
#pragma unroll
        for (int kk = 0; kk < 32; kk += 16) {
            unsigned a[2][4];
#pragma unroll
            for (int mt = 0; mt < 2; mt++) {
                const int r = wm * 32 + mt * 16 + gid;
                a[mt][0] = *(const unsigned*)&As[cur][r    ][kk + tig * 2];
                a[mt][1] = *(const unsigned*)&As[cur][r + 8][kk + tig * 2];
                a[mt][2] = *(const unsigned*)&As[cur][r    ][kk + tig * 2 + 8];
                a[mt][3] = *(const unsigned*)&As[cur][r + 8][kk + tig * 2 + 8];
            }
#pragma unroll
            for (int nt = 0; nt < 8; nt++) {
                const unsigned b0 = *(const unsigned*)&Bs[cur][wn * 64 + nt * 8 + gid][kk + tig * 2];
                const unsigned b1 = *(const unsigned*)&Bs[cur][wn * 64 + nt * 8 + gid][kk + tig * 2 + 8];
#pragma unroll
                for (int mt = 0; mt < 2; mt++) {
                    asm volatile(
                        "mma.sync.aligned.m16n8k16.row.col.f32.f16.f16.f32 "
                        "{%0,%1,%2,%3}, {%4,%5,%6,%7}, {%8,%9}, {%0,%1,%2,%3};"
                        : "+f"(c[mt][nt][0]), "+f"(c[mt][nt][1]),
                          "+f"(c[mt][nt][2]), "+f"(c[mt][nt][3])
                        : "r"(a[mt][0]), "r"(a[mt][1]), "r"(a[mt][2]), "r"(a[mt][3]),
                          "r"(b0), "r"(b1));
                }
            }
        }
        if (it < FF / 32 - 1) stA(nxt);
    }

    // epilogue: bias + attribute mix, fp16 flow store, partial score -> smem atomics
#pragma unroll
    for (int mt = 0; mt < 2; mt++) {
        const int rl1 = wm * 32 + mt * 16 + gid;
        const int rl2 = rl1 + 8;
        const int r1 = row0 + rl1, r2 = row0 + rl2;
        float a0r1 = 0.f, a1r1 = 0.f, a0r2 = 0.f, a1r2 = 0.f;
        if (r1 < NN) { a0r1 = adj[r1]; a1r1 = adj[NN + r1]; }
        if (r2 < NN) { a0r2 = adj[r2]; a1r2 = adj[NN + r2]; }
        float s1 = 0.f, s2 = 0.f;
#pragma unroll
        for (int nt = 0; nt < 8; nt++) {
            const int col = wn * 64 + nt * 8 + tig * 2;
            const float ch0a = ch_s[0][col], ch0b = ch_s[0][col + 1];
            const float ch1a = ch_s[1][col], ch1b = ch_s[1][col + 1];
            const float ba = bias_s[col], bbv = bias_s[col + 1];
            const float v1a = 0.5f * (c[mt][nt][0] + ba  + a0r1 * ch0a + a1r1 * ch1a);
            const float v1b = 0.5f * (c[mt][nt][1] + bbv + a0r1 * ch0b + a1r1 * ch1b);
            const float v2a = 0.5f * (c[mt][nt][2] + ba  + a0r2 * ch0a + a1r2 * ch1a);
            const float v2b = 0.5f * (c[mt][nt][3] + bbv + a0r2 * ch0b + a1r2 * ch1b);
            if (r1 < NN)
                *(__half2*)&g_flow_h[(size_t)r1 * DD + col] = __floats2half2_rn(v1a, v1b);
            if (r2 < NN)
                *(__half2*)&g_flow_h[(size_t)r2 * DD + col] = __floats2half2_rn(v2a, v2b);
            s1 += v1a * att_s[col] + v1b * att_s[col + 1];
            s2 += v2a * att_s[col] + v2b * att_s[col + 1];
        }
        s1 += __shfl_xor_sync(0xffffffffu, s1, 1);
        s1 += __shfl_xor_sync(0xffffffffu, s1, 2);
        s2 += __shfl_xor_sync(0xffffffffu, s2, 1);
        s2 += __shfl_xor_sync(0xffffffffu, s2, 2);
        if (tig == 0) {
            atomicAdd(&sc[rl1], s1);
            atomicAdd(&sc[rl2], s2);
        }
    }
    __syncthreads();
    if (tid < 128) {
        const int r = row0 + tid;
        if (r < NN) g_score[r] = sc[tid] + att1b[0];
    }
}

// ---------------- K6: per-row gather + softmax + weighted sum -> fp16 agg ---------------
__global__ __launch_bounds__(256) void agg_kernel(const int* __restrict__ history) {
    const int warp = threadIdx.x >> 5, lane = threadIdx.x & 31;
    const int b = blockIdx.x * 8 + warp;
    const int h = history[b * KK + lane];
    const float s = g_score[h];
    float mx = s;
#pragma unroll
    for (int o = 16; o; o >>= 1) mx = fmaxf(mx, __shfl_xor_sync(0xffffffffu, mx, o));
    const float e = expf(s - mx);
    float sum = e;
#pragma unroll
    for (int o = 16; o; o >>= 1) sum += __shfl_xor_sync(0xffffffffu, sum, o);
    const float att = e / sum;
    float4 acc = make_float4(0.f, 0.f, 0.f, 0.f);
    const uint2* fa = (const uint2*)g_flow_h;
#pragma unroll
    for (int k = 0; k < KK; k++) {
        const int   idx = __shfl_sync(0xffffffffu, h, k);
        const float w   = __shfl_sync(0xffffffffu, att, k);
        const uint2 f = fa[idx * 32 + lane];
        const float2 p0 = __half22float2(*(const __half2*)&f.x);
        const float2 p1 = __half22float2(*(const __half2*)&f.y);
        acc.x += w * p0.x; acc.y += w * p0.y; acc.z += w * p1.x; acc.w += w * p1.y;
    }
    __half2 h0 = __floats2half2_rn(acc.x, acc.y);
    __half2 h1 = __floats2half2_rn(acc.z, acc.w);
    uint2 st;
    st.x = *(unsigned*)&h0;
    st.y = *(unsigned*)&h1;
    *(uint2*)&g_agg_h[(size_t)b * DD + lane * 4] = st;
}

// ---------------- K7: fp16 tensor out-GEMM + fused sigmoid-Lat + relu/Lat-dot -----------
__global__ __launch_bounds__(256) void outpred_kernel(const float* __restrict__ lin1b,
                                                      float* __restrict__ out) {
    __shared__ __half As[128][40];
    __shared__ __half Bs[128][40];
    __shared__ float Lat_s[2 * MM * DD];
    __shared__ float lb_s[DD];
    const int*   catr = g_ptrs.catr;
    const int*   catn = g_ptrs.catn;
    const int*   pav  = g_ptrs.pa;
    const int tid  = threadIdx.x;
    const int warp = tid >> 5, lane = tid & 31;
    const int gid  = lane >> 2, tig = lane & 3;
    const int row0 = blockIdx.x * 128;
    // fused sigmoid Lat table (was sig_kernel)
    for (int i = tid; i < 2 * MM * DD; i += 256) {
        const int d  = i & 127;
        const int p  = (i >> 7) % MM;
        const int cc = i / (MM * DD);
        Lat_s[i] = 1.f / (1.f + expf(-(g_at[cc * DD + d] + g_bb[p * DD + d])));
    }
    if (tid < DD) lb_s[tid] = lin1b[tid];

    float c[16][4];
#pragma unroll
    for (int nt = 0; nt < 16; nt++)
#pragma unroll
        for (int j = 0; j < 4; j++) c[nt][j] = 0.f;

    const int arow = tid >> 1;
    const int acol = (tid & 1) * 16;
#pragma unroll
    for (int kt = 0; kt < DD; kt += 32) {
        *(uint4*)&As[arow][acol]     = *(const uint4*)&g_agg_h[(size_t)(row0 + arow) * DD + kt + acol];
        *(uint4*)&As[arow][acol + 8] = *(const uint4*)&g_agg_h[(size_t)(row0 + arow) * DD + kt + acol + 8];
        *(uint4*)&Bs[arow][acol]     = *(const uint4*)&g_W1hT[(size_t)arow * DD + kt + acol];
        *(uint4*)&Bs[arow][acol + 8] = *(const uint4*)&g_W1hT[(size_t)arow * DD + kt + acol + 8];
        __syncthreads();
#pragma unroll
        for (int kk = 0; kk < 32; kk += 16) {
            const unsigned a0 = *(const unsigned*)&As[warp * 16 + gid    ][kk + tig * 2];
            const unsigned a1 = *(const unsigned*)&As[warp * 16 + gid + 8][kk + tig * 2];
            const unsigned a2 = *(const unsigned*)&As[warp * 16 + gid    ][kk + tig * 2 + 8];
            const unsigned a3 = *(const unsigned*)&As[warp * 16 + gid + 8][kk + tig * 2 + 8];
#pragma unroll
            for (int nt = 0; nt < 16; nt++) {
                const unsigned b0 = *(const unsigned*)&Bs[nt * 8 + gid][kk + tig * 2];
                const unsigned b1 = *(const unsigned*)&Bs[nt * 8 + gid][kk + tig * 2 + 8];
                asm volatile(
                    "mma.sync.aligned.m16n8k16.row.col.f32.f16.f16.f32 "
                    "{%0,%1,%2,%3}, {%4,%5,%6,%7}, {%8,%9}, {%0,%1,%2,%3};"
                    : "+f"(c[nt][0]), "+f"(c[nt][1]), "+f"(c[nt][2]), "+f"(c[nt][3])
                    : "r"(a0), "r"(a1), "r"(a2), "r"(a3), "r"(b0), "r"(b1));
            }
        }
        __syncthreads();
    }

    const int r1 = row0 + warp * 16 + gid;
    const int r2 = r1 + 8;
    const int p1_ = pav[r1], p2_ = pav[r2];
    const float* Lr1 = &Lat_s[(catr[r1] * MM + p1_) * DD];
    const float* Ln1 = &Lat_s[(catn[r1] * MM + p1_) * DD];
    const float* Lr2 = &Lat_s[(catr[r2] * MM + p2_) * DD];
    const float* Ln2 = &Lat_s[(catn[r2] * MM + p2_) * DD];
    float sr1 = 0.f, sn1 = 0.f, sr2 = 0.f, sn2 = 0.f;
#pragma unroll
    for (int nt = 0; nt < 16; nt++) {
        const int col = nt * 8 + tig * 2;
        const float b0 = lb_s[col], b1 = lb_s[col + 1];
        const float o0 = fmaxf(c[nt][0] + b0, 0.f);
        const float o1 = fmaxf(c[nt][1] + b1, 0.f);
        const float o2 = fmaxf(c[nt][2] + b0, 0.f);
        const float o3 = fmaxf(c[nt][3] + b1, 0.f);
        sr1 += o0 * Lr1[col] + o1 * Lr1[col + 1];
        sn1 += o0 * Ln1[col] + o1 * Ln1[col + 1];
        sr2 += o2 * Lr2[col] + o3 * Lr2[col + 1];
        sn2 += o2 * Ln2[col] + o3 * Ln2[col + 1];
    }
#pragma unroll
    for (int o = 1; o < 4; o <<= 1) {
        sr1 += __shfl_xor_sync(0xffffffffu, sr1, o);
        sn1 += __shfl_xor_sync(0xffffffffu, sn1, o);
        sr2 += __shfl_xor_sync(0xffffffffu, sr2, o);
        sn2 += __shfl_xor_sync(0xffffffffu, sn2, o);
    }
    if (tig == 0) {
        out[r1]      = sr1;
        out[BB + r1] = sn1;
        out[r2]      = sr2;
        out[BB + r2] = sn2;
    }
}

// ---------------- host ----------------
extern "C" void kernel_launch(void* const* d_in, const int* in_sizes, int n_in,
                              void* d_out, int out_size) {
    const float* feat = nullptr;
    const float* adj  = nullptr;
    const int*   hist = nullptr;
    const float* b1   = nullptr;
    const void*  s32[8] = {nullptr};
    int n32 = 0;
    const float* s128[4] = {nullptr};
    int n128 = 0;

    for (int i = 0; i < n_in; i++) {
        const int sz = in_sizes[i];
        if (sz == NN * FF)      feat = (const float*)d_in[i];
        else if (sz == MM * NN) adj  = (const float*)d_in[i];
        else if (sz == BB * KK) hist = (const int*)d_in[i];
        else if (sz == BB)      { if (n32 < 8)  s32[n32++]  = d_in[i]; }
        else if (sz == DD)      { if (n128 < 4) s128[n128++] = (const float*)d_in[i]; }
        else if (sz == 1)       b1 = (const float*)d_in[i];
    }
    const float* bemb  = s128[0];
    const float* att1w = s128[1];
    const float* lin1b = s128[2];

    fixup_kernel<<<1, 256>>>(s32[0], s32[1], s32[2], s32[3], s32[4], s32[5], s32[6]);
    wcvt_kernel<<<(FF * DD + DD * DD + 255) / 256, 256>>>();
    adjfeat_kernel<<<(NN + 511) / 512, 256>>>(adj, feat);
    char_kernel2<<<MM * 8, 128>>>(bemb);
    gemm_fused<<<(NN + 127) / 128, 256>>>(feat, bemb, adj, att1w, b1);
    lat_kernel2<<<(MM + 2) * 4, 128>>>();
    agg_kernel<<<BB / 8, 256>>>(hist);
    outpred_kernel<<<BB / 128, 256>>>(lin1b, (float*)d_out);
}